// round 11
// baseline (speedup 1.0000x reference)
#include <cuda_runtime.h>
#include <cstdint>

#define NB 64
#define TT 100
#define NN 25
#define VV 128
#define CC 128
#define EE 64
#define NG (NB*TT)
#define GPT 5                 // graphs per tile
#define MR (GPT*NN)           // 125 rows per tile
#define NTILES (NG/GPT)       // 1280
#define XSTR 132              // X/V row stride: 16B-aligned rows; rows tr+16i -> conflict-free
#define XV_F (128*XSTR)       // 16896 floats
#define WS_F (VV*CC)          // 16384
#define A2D_F 1280            // 625 u64 (duplicated A2) = 1250 floats, padded
#define CNT ((float)(NB*NN*CC))

__device__ float g_A2[NN*NN];
__device__ float g_rA[NN];
__device__ float g_b1w2[CC];
__device__ float g_W12[VV*CC];
__device__ float g_stats[2*TT];

typedef unsigned long long u64;

__device__ __forceinline__ u64 pk2(float v){
    u64 r; unsigned u = __float_as_uint(v);
    asm("mov.b64 %0, {%1, %1};" : "=l"(r) : "r"(u));
    return r;
}
__device__ __forceinline__ void ffma2(u64 &d, u64 a, u64 b){
    asm("fma.rn.f32x2 %0, %1, %2, %0;" : "+l"(d) : "l"(a), "l"(b));
}
__device__ __forceinline__ void upk(u64 v, float &lo, float &hi){
    unsigned a,b; asm("mov.b64 {%0, %1}, %2;" : "=r"(a), "=r"(b) : "l"(v));
    lo = __uint_as_float(a); hi = __uint_as_float(b);
}
__device__ __forceinline__ uint32_t smem_u32(const void* p){
    uint32_t a;
    asm("{ .reg .u64 t; cvta.to.shared.u64 t, %1; cvt.u32.u64 %0, t; }" : "=r"(a) : "l"(p));
    return a;
}
__device__ __forceinline__ void cp16(uint32_t dst, const void* src){
    asm volatile("cp.async.cg.shared.global [%0], [%1], 16;" :: "r"(dst), "l"(src));
}
#define CP_COMMIT() asm volatile("cp.async.commit_group;" ::: "memory")
#define CP_WAIT0()  asm volatile("cp.async.wait_group 0;"  ::: "memory")

// ---------------------------------------------------------------------------
// Parallel prep (256 thr): every block computes one W12 row; block 0 builds
// normalized adjacency via shared atomics, A2, rowsum, b1^T W2, and zeroes
// ALL stats (replay idempotence).  Edge dtype auto-detected.
// ---------------------------------------------------------------------------
__global__ void prep_k(const int* __restrict__ ei,
                       const float* __restrict__ W1,
                       const float* __restrict__ W2,
                       const float* __restrict__ b1){
    __shared__ float A[NN*NN];
    __shared__ float row[CC];
    __shared__ float deg[NN];
    __shared__ int   es[EE], et[EE];
    __shared__ int   flag;
    const int tid = threadIdx.x;
    const int bi  = blockIdx.x;

    if (tid < CC) row[tid] = W1[bi*CC + tid];
    __syncthreads();
    if (tid < CC){
        float s = 0.0f;
        #pragma unroll 8
        for (int j = 0; j < CC; j++) s += row[j]*W2[j*CC+tid];
        g_W12[bi*CC+tid] = s;
    }

    if (bi != 0) return;

    if (tid < 2*TT) g_stats[tid] = 0.0f;
    if (tid == 0)   flag = 1;
    if (tid < NN)   deg[tid] = 1.0f;            // self-loops
    for (int i = tid; i < NN*NN; i += blockDim.x) A[i] = 0.0f;
    __syncthreads();

    if (tid < EE){  // int64 layout = [v,0] pairs in first 128 words
        int a = ei[2*tid], b = ei[2*tid+1];
        if (b != 0 || (unsigned)a >= (unsigned)NN) atomicExch(&flag, 0);
    }
    __syncthreads();
    const bool is64 = (flag != 0);
    if (tid < EE){
        es[tid] = is64 ? ei[2*tid]        : ei[tid];
        et[tid] = is64 ? ei[2*(EE+tid)]   : ei[EE+tid];
        atomicAdd(&deg[et[tid]], 1.0f);
    }
    __syncthreads();
    if (tid < EE){
        int s = es[tid], t = et[tid];
        atomicAdd(&A[t*NN+s], rsqrtf(deg[s])*rsqrtf(deg[t]));
    }
    if (tid < NN){
        float r = rsqrtf(deg[tid]);
        atomicAdd(&A[tid*NN+tid], r*r);
    }
    __syncthreads();

    for (int idx = tid; idx < NN*NN; idx += blockDim.x){
        int n = idx / NN, m = idx % NN;
        float s = 0.0f;
        #pragma unroll
        for (int j = 0; j < NN; j++) s += A[n*NN+j]*A[j*NN+m];
        g_A2[idx] = s;
    }
    if (tid < NN){
        float s = 0.0f;
        #pragma unroll
        for (int m = 0; m < NN; m++) s += A[tid*NN+m];
        g_rA[tid] = s;
    }
    if (tid < CC){
        float s = 0.0f;
        for (int k = 0; k < CC; k++) s += b1[k]*W2[k*CC+tid];
        g_b1w2[tid] = s;
    }
}

// ---------------------------------------------------------------------------
// Main persistent kernel, 256 threads, 1 block/SM (~136KB smem).
//   stage 1: V[125,128] = X @ W12 — 8 rows (tr+16i) x 8 cols per thread,
//            TWO k-steps per iteration: X read as float2 (8B, conflict-free),
//            W12 from smem via LDS.128.  Crossbar: 96 cyc/SM/k < 128 fma cyc.
//   stage 2: warps 0..4, one graph each; n chunked 9/8/8; A2 from a
//            pre-duplicated u64 table.
// ---------------------------------------------------------------------------
__global__ __launch_bounds__(256, 1)
void gcn_k(const float* __restrict__ x,
           const float* __restrict__ b2g,
           float* __restrict__ out){
    extern __shared__ float sm[];
    float* ws   = sm;                 // W12 [k][c], 128x128
    float* XV   = ws + WS_F;          // X tile then V tile, 128x132
    float* A2df = XV + XV_F;          // duplicated A2: 625 u64
    u64*   A2d  = (u64*)A2df;
    float* rAs  = A2df + A2D_F;       // 32
    float* bws  = rAs + 32;           // 128
    float* b2s  = bws + CC;           // 128

    const int tid  = threadIdx.x;
    const int tc   = tid & 15;
    const int tr   = tid >> 4;        // 0..15
    const int c0   = tc << 3;
    const int lane = tid & 31;
    const int wid  = tid >> 5;        // 0..7
    const uint32_t xb = smem_u32(XV);

    for (int i = tid; i < WS_F/4; i += 256)
        ((float4*)ws)[i] = ((const float4*)g_W12)[i];
    for (int i = tid; i < NN*NN; i += 256) A2d[i] = pk2(g_A2[i]);
    if (tid < NN) rAs[tid] = g_rA[tid];
    if (tid < CC) bws[tid] = g_b1w2[tid];
    else if (tid < 2*CC) b2s[tid-CC] = b2g[tid-CC];
    __syncthreads();

    for (int tile = blockIdx.x; tile < NTILES; tile += gridDim.x){
        // ---- stage X via cp.async.cg ----
        const float4* xp = (const float4*)(x + (size_t)tile*(MR*CC));
        for (int i = tid; i < (MR*CC)/4; i += 256){
            int row = i >> 5, cb = (i & 31) << 2;
            cp16(xb + (uint32_t)(row*XSTR + cb)*4u, xp + i);
        }
        CP_COMMIT();
        CP_WAIT0();
        __syncthreads();

        // ---- stage 1: V = X @ W12, two k per iter ----
        u64 acc[8][4];
        #pragma unroll
        for (int i = 0; i < 8; i++)
            #pragma unroll
            for (int q = 0; q < 4; q++) acc[i][q] = 0ull;

        #pragma unroll 2
        for (int k2 = 0; k2 < VV/2; k2++){
            const int k = k2 << 1;
            const float* wr = ws + (k << 7) + c0;
            ulonglong2 wa = *(const ulonglong2*)wr;
            ulonglong2 wb = *(const ulonglong2*)(wr + 4);
            ulonglong2 wc = *(const ulonglong2*)(wr + 128);
            ulonglong2 wd = *(const ulonglong2*)(wr + 132);
            float2 af[8];
            #pragma unroll
            for (int i = 0; i < 8; i++)
                af[i] = *(const float2*)(XV + (tr + 16*i)*XSTR + k);
            #pragma unroll
            for (int i = 0; i < 8; i++){
                u64 a0 = pk2(af[i].x);
                ffma2(acc[i][0], a0, wa.x);
                ffma2(acc[i][1], a0, wa.y);
                ffma2(acc[i][2], a0, wb.x);
                ffma2(acc[i][3], a0, wb.y);
                u64 a1 = pk2(af[i].y);
                ffma2(acc[i][0], a1, wc.x);
                ffma2(acc[i][1], a1, wc.y);
                ffma2(acc[i][2], a1, wd.x);
                ffma2(acc[i][3], a1, wd.y);
            }
        }
        __syncthreads();   // all X reads done -> reuse buffer as V

        #pragma unroll
        for (int i = 0; i < 8; i++){
            int row = tr + 16*i;
            if (i < 7 || row < MR){
                ulonglong2* vp = (ulonglong2*)(XV + row*XSTR + c0);
                ulonglong2 t0; t0.x = acc[i][0]; t0.y = acc[i][1];
                ulonglong2 t1; t1.x = acc[i][2]; t1.y = acc[i][3];
                vp[0] = t0; vp[1] = t1;
            }
        }
        __syncthreads();

        // ---- stage 2: warps 0..4 own one graph; n chunked 9/8/8 ----
        if (wid < GPT){
            const int g  = tile*GPT + wid;
            const int cb = lane << 2;            // 4 cols per lane
            float bw0 = bws[cb],   bw1 = bws[cb+1],
                  bw2 = bws[cb+2], bw3 = bws[cb+3];
            float bb0 = b2s[cb],   bb1 = b2s[cb+1],
                  bb2 = b2s[cb+2], bb3 = b2s[cb+3];
            float* zp = out + (size_t)g*(NN*CC) + cb;
            float ls = 0.0f, lss = 0.0f;

            #pragma unroll
            for (int ch = 0; ch < 3; ch++){
                const int n0 = (ch == 0) ? 0 : 9 + (ch-1)*8;
                const int nc = (ch == 0) ? 9 : 8;
                u64 z[9][2];
                #pragma unroll
                for (int n = 0; n < 9; n++){ z[n][0] = 0ull; z[n][1] = 0ull; }

                #pragma unroll 5
                for (int m = 0; m < NN; m++){
                    ulonglong2 v = *(const ulonglong2*)(XV + (wid*NN + m)*XSTR + cb);
                    const u64* ad = A2d + (n0*NN + m);
                    #pragma unroll
                    for (int n = 0; n < 9; n++){
                        if (n < nc){
                            u64 a = ad[n*NN];
                            ffma2(z[n][0], a, v.x);
                            ffma2(z[n][1], a, v.y);
                        }
                    }
                }
                #pragma unroll
                for (int n = 0; n < 9; n++){
                    if (n < nc){
                        float r = rAs[n0 + n];
                        float o0,o1,o2,o3;
                        upk(z[n][0], o0, o1);
                        upk(z[n][1], o2, o3);
                        o0 = fmaf(r, bw0, o0) + bb0;
                        o1 = fmaf(r, bw1, o1) + bb1;
                        o2 = fmaf(r, bw2, o2) + bb2;
                        o3 = fmaf(r, bw3, o3) + bb3;
                        ls += o0 + o1 + o2 + o3;
                        lss = fmaf(o0,o0, fmaf(o1,o1, fmaf(o2,o2, fmaf(o3,o3, lss))));
                        *(float4*)(zp + (n0+n)*CC) = make_float4(o0,o1,o2,o3);
                    }
                }
            }
            #pragma unroll
            for (int s = 16; s; s >>= 1){
                ls  += __shfl_xor_sync(0xffffffffu, ls,  s);
                lss += __shfl_xor_sync(0xffffffffu, lss, s);
            }
            if (lane == 0){
                int t = g % TT;
                atomicAdd(&g_stats[t],      ls);
                atomicAdd(&g_stats[TT + t], lss);
            }
        }
        __syncthreads();   // V reads done before next tile's X staging
    }
}

// BN finalize (per-block redundant) + in-place BN + ReLU, 8 float4 per iter.
__global__ void bn_k(const float* __restrict__ gamma,
                     const float* __restrict__ beta,
                     float* __restrict__ out){
    __shared__ float sc[TT], sh[TT];
    for (int t = threadIdx.x; t < TT; t += blockDim.x){
        float mean = g_stats[t] / CNT;
        float var  = g_stats[TT + t] / CNT - mean*mean;
        float s    = rsqrtf(var + 1e-5f) * gamma[t];
        sc[t] = s;
        sh[t] = beta[t] - mean*s;
    }
    __syncthreads();

    const int total32 = (NB*TT*NN*CC)/32;   // 640,000 groups of 8 float4
    int stride = gridDim.x * blockDim.x;
    for (int i = blockIdx.x*blockDim.x + threadIdx.x; i < total32; i += stride){
        int t = (i / 100) % TT;             // 100 = N*C/32 groups per (b,t)
        float s = sc[t], h = sh[t];
        float4* p = (float4*)out + (size_t)i*8;
        float4 v[8];
        #pragma unroll
        for (int q = 0; q < 8; q++) v[q] = p[q];
        #pragma unroll
        for (int q = 0; q < 8; q++){
            v[q].x = fmaxf(fmaf(v[q].x, s, h), 0.0f);
            v[q].y = fmaxf(fmaf(v[q].y, s, h), 0.0f);
            v[q].z = fmaxf(fmaf(v[q].z, s, h), 0.0f);
            v[q].w = fmaxf(fmaf(v[q].w, s, h), 0.0f);
        }
        #pragma unroll
        for (int q = 0; q < 8; q++) p[q] = v[q];
    }
}

extern "C" void kernel_launch(void* const* d_in, const int* in_sizes, int n_in,
                              void* d_out, int out_size){
    const float* x  = (const float*)d_in[0];
    const int*   ei = (const int*)  d_in[1];
    const float* W1 = (const float*)d_in[2];
    const float* b1 = (const float*)d_in[3];
    const float* W2 = (const float*)d_in[4];
    const float* b2 = (const float*)d_in[5];
    const float* ga = (const float*)d_in[6];
    const float* be = (const float*)d_in[7];
    float* out = (float*)d_out;

    int nsm = 148;
    cudaDeviceGetAttribute(&nsm, cudaDevAttrMultiProcessorCount, 0);

    const int smemB = (WS_F + XV_F + A2D_F + 32 + 2*CC) * (int)sizeof(float);
    cudaFuncSetAttribute(gcn_k, cudaFuncAttributeMaxDynamicSharedMemorySize, smemB);

    prep_k<<<CC, 256>>>(ei, W1, W2, b1);
    gcn_k<<<nsm, 256, smemB>>>(x, b2, out);
    bn_k<<<nsm*8, 256>>>(ga, be, out);
}

// round 12
// speedup vs baseline: 1.4018x; 1.4018x over previous
#include <cuda_runtime.h>
#include <cstdint>

#define NB 64
#define TT 100
#define NN 25
#define VV 128
#define CC 128
#define EE 64
#define NG (NB*TT)
#define GPT 5                 // graphs per tile
#define MR (GPT*NN)           // 125 rows per tile
#define NTILES (NG/GPT)       // 1280
#define XSTR 129              // X-tile stride: bank(r,k) = (r+k)%32 -> conflict-free A frags
#define VSTR 132              // V-tile stride: 16B-aligned rows for LDS.128
#define WS_F (VV*CC)          // 16384
#define XV_F 16512            // max(128*129, 125*132)
#define A2_F 640              // 625 padded to multiple of 4 -> downstream float4 alignment
#define CNT ((float)(NB*NN*CC))

__device__ float g_A2[NN*NN];
__device__ float g_rA[NN];
__device__ float g_b1w2[CC];
__device__ float g_W12[VV*CC];
__device__ float g_stats[2*TT];

typedef unsigned long long u64;

__device__ __forceinline__ u64 pk2(float v){
    u64 r; unsigned u = __float_as_uint(v);
    asm("mov.b64 %0, {%1, %1};" : "=l"(r) : "r"(u));
    return r;
}
__device__ __forceinline__ void ffma2(u64 &d, u64 a, u64 b){
    asm("fma.rn.f32x2 %0, %1, %2, %0;" : "+l"(d) : "l"(a), "l"(b));
}
__device__ __forceinline__ void upk(u64 v, float &lo, float &hi){
    unsigned a,b; asm("mov.b64 {%0, %1}, %2;" : "=r"(a), "=r"(b) : "l"(v));
    lo = __uint_as_float(a); hi = __uint_as_float(b);
}

// ---------------------------------------------------------------------------
// Parallel prep (256 thr): every block computes one W12 row; block 0 builds
// normalized adjacency via shared atomics, A2, rowsum, b1^T W2, and zeroes
// ALL stats (replay idempotence).  Edge dtype auto-detected.
// (Measured 15.9-17.0 us in R8/R10 vs 22.7 us for the serial builder.)
// ---------------------------------------------------------------------------
__global__ void prep_k(const int* __restrict__ ei,
                       const float* __restrict__ W1,
                       const float* __restrict__ W2,
                       const float* __restrict__ b1){
    __shared__ float A[NN*NN];
    __shared__ float row[CC];
    __shared__ float deg[NN];
    __shared__ int   es[EE], et[EE];
    __shared__ int   flag;
    const int tid = threadIdx.x;
    const int bi  = blockIdx.x;

    if (tid < CC) row[tid] = W1[bi*CC + tid];
    __syncthreads();
    if (tid < CC){
        float s = 0.0f;
        #pragma unroll 8
        for (int j = 0; j < CC; j++) s += row[j]*W2[j*CC+tid];
        g_W12[bi*CC+tid] = s;
    }

    if (bi != 0) return;

    if (tid < 2*TT) g_stats[tid] = 0.0f;
    if (tid == 0)   flag = 1;
    if (tid < NN)   deg[tid] = 1.0f;            // self-loops
    for (int i = tid; i < NN*NN; i += blockDim.x) A[i] = 0.0f;
    __syncthreads();

    if (tid < EE){  // int64 layout = [v,0] pairs in first 128 words
        int a = ei[2*tid], b = ei[2*tid+1];
        if (b != 0 || (unsigned)a >= (unsigned)NN) atomicExch(&flag, 0);
    }
    __syncthreads();
    const bool is64 = (flag != 0);
    if (tid < EE){
        es[tid] = is64 ? ei[2*tid]        : ei[tid];
        et[tid] = is64 ? ei[2*(EE+tid)]   : ei[EE+tid];
        atomicAdd(&deg[et[tid]], 1.0f);
    }
    __syncthreads();
    if (tid < EE){
        int s = es[tid], t = et[tid];
        atomicAdd(&A[t*NN+s], rsqrtf(deg[s])*rsqrtf(deg[t]));
    }
    if (tid < NN){
        float r = rsqrtf(deg[tid]);
        atomicAdd(&A[tid*NN+tid], r*r);
    }
    __syncthreads();

    for (int idx = tid; idx < NN*NN; idx += blockDim.x){
        int n = idx / NN, m = idx % NN;
        float s = 0.0f;
        #pragma unroll
        for (int j = 0; j < NN; j++) s += A[n*NN+j]*A[j*NN+m];
        g_A2[idx] = s;
    }
    if (tid < NN){
        float s = 0.0f;
        #pragma unroll
        for (int m = 0; m < NN; m++) s += A[tid*NN+m];
        g_rA[tid] = s;
    }
    if (tid < CC){
        float s = 0.0f;
        for (int k = 0; k < CC; k++) s += b1[k]*W2[k*CC+tid];
        g_b1w2[tid] = s;
    }
}

// ---------------------------------------------------------------------------
// Main persistent kernel — VERBATIM the R6-winning structure (233.9 us run).
// Per tile = 5 graphs = 125 rows:
//   stage 1: V[125,128] = X[125,128] @ W12[128,128]  (8x8 FFMA2 blocking,
//            X staged at stride 129 -> conflict-free scalar broadcasts,
//            W via LDS.128 from smem)
//   stage 2: warp w<5 owns graph w: Z = A2 @ V + rA(x)b1W2 + b2 -> gmem,
//            per-graph sum/sumsq -> 2 global atomics.
// 256 thr, 1 block/SM (~134KB smem), W12/A2 loaded once per block.
// ---------------------------------------------------------------------------
__global__ __launch_bounds__(256, 1)
void gcn_k(const float* __restrict__ x,
           const float* __restrict__ b2g,
           float* __restrict__ out){
    extern __shared__ float sm[];
    float* ws  = sm;            // W12 [k][c], 128x128
    float* XV  = ws + WS_F;     // X tile (stride 129) then V tile (stride 132)
    float* A2s = XV + XV_F;     // 625 used, 640 reserved (alignment pad)
    float* rAs = A2s + A2_F;    // 32
    float* bws = rAs + 32;      // 128 (16B-aligned)
    float* b2s = bws + CC;      // 128 (16B-aligned)

    const int tid  = threadIdx.x;
    const int tc   = tid & 15;
    const int tr   = tid >> 4;
    const int c0   = tc << 3;
    const int lane = tid & 31;
    const int wid  = tid >> 5;

    for (int i = tid; i < WS_F/4; i += 256)
        ((float4*)ws)[i] = ((const float4*)g_W12)[i];
    for (int i = tid; i < NN*NN; i += 256) A2s[i] = g_A2[i];
    if (tid < NN) rAs[tid] = g_rA[tid];
    if (tid < CC) bws[tid] = g_b1w2[tid];
    else if (tid < 2*CC) b2s[tid-CC] = b2g[tid-CC];
    __syncthreads();

    for (int tile = blockIdx.x; tile < NTILES; tile += gridDim.x){
        // ---- stage X: 125x128 rows, stride-129 layout ----
        const float4* xp = (const float4*)(x + (size_t)tile*(MR*CC));
        for (int i = tid; i < (MR*CC)/4; i += 256){
            float4 v = xp[i];
            int row = i >> 5, cb = (i & 31) << 2;
            float* d = XV + row*XSTR + cb;
            d[0]=v.x; d[1]=v.y; d[2]=v.z; d[3]=v.w;
        }
        __syncthreads();

        // ---- stage 1: V = X @ W12 (rows 120..127 of 8x8 tile may be junk for
        //      tr=15; never stored) ----
        u64 acc[8][4];
        #pragma unroll
        for (int i = 0; i < 8; i++)
            #pragma unroll
            for (int q = 0; q < 4; q++) acc[i][q] = 0ull;

        #pragma unroll 4
        for (int k = 0; k < VV; k++){
            const float* wr = ws + (k << 7) + c0;
            ulonglong2 wa = *(const ulonglong2*)wr;
            ulonglong2 wb = *(const ulonglong2*)(wr + 4);
            float af[8];
            #pragma unroll
            for (int i = 0; i < 8; i++) af[i] = XV[(tr*8 + i)*XSTR + k];
            #pragma unroll
            for (int i = 0; i < 8; i++){
                u64 a = pk2(af[i]);
                ffma2(acc[i][0], a, wa.x);
                ffma2(acc[i][1], a, wa.y);
                ffma2(acc[i][2], a, wb.x);
                ffma2(acc[i][3], a, wb.y);
            }
        }
        __syncthreads();   // X fully consumed -> reuse buffer as V (stride 132)

        #pragma unroll
        for (int i = 0; i < 8; i++){
            int row = tr*8 + i;
            if (row < MR){
                ulonglong2* vp = (ulonglong2*)(XV + row*VSTR + c0);
                ulonglong2 t0; t0.x = acc[i][0]; t0.y = acc[i][1];
                ulonglong2 t1; t1.x = acc[i][2]; t1.y = acc[i][3];
                vp[0] = t0; vp[1] = t1;
            }
        }
        __syncthreads();

        // ---- stage 2: warps 0..4 each own one graph ----
        if (wid < GPT){
            const int g = tile*GPT + wid;
            u64 z[NN][2];
            #pragma unroll
            for (int n = 0; n < NN; n++){ z[n][0] = 0ull; z[n][1] = 0ull; }

            #pragma unroll 5
            for (int m = 0; m < NN; m++){
                ulonglong2 v = *(const ulonglong2*)(XV + (wid*NN + m)*VSTR + (lane << 2));
                #pragma unroll
                for (int n = 0; n < NN; n++){
                    u64 a = pk2(A2s[n*NN + m]);
                    ffma2(z[n][0], a, v.x);
                    ffma2(z[n][1], a, v.y);
                }
            }

            float4 bw = *(const float4*)(bws + (lane << 2));
            float4 bb = *(const float4*)(b2s + (lane << 2));
            float* zp = out + (size_t)g*(NN*CC) + (lane << 2);
            float ls = 0.0f, lss = 0.0f;
            #pragma unroll
            for (int n = 0; n < NN; n++){
                float r = rAs[n];
                float o0,o1,o2,o3;
                upk(z[n][0], o0, o1);
                upk(z[n][1], o2, o3);
                o0 = fmaf(r, bw.x, o0) + bb.x;
                o1 = fmaf(r, bw.y, o1) + bb.y;
                o2 = fmaf(r, bw.z, o2) + bb.z;
                o3 = fmaf(r, bw.w, o3) + bb.w;
                ls += o0 + o1 + o2 + o3;
                lss = fmaf(o0,o0, fmaf(o1,o1, fmaf(o2,o2, fmaf(o3,o3, lss))));
                *(float4*)(zp + n*CC) = make_float4(o0,o1,o2,o3);
            }
            #pragma unroll
            for (int s = 16; s; s >>= 1){
                ls  += __shfl_xor_sync(0xffffffffu, ls,  s);
                lss += __shfl_xor_sync(0xffffffffu, lss, s);
            }
            if (lane == 0){
                int t = g % TT;
                atomicAdd(&g_stats[t],      ls);
                atomicAdd(&g_stats[TT + t], lss);
            }
        }
        __syncthreads();   // V reads done before next tile's X staging
    }
}

// BN finalize (per-block redundant) + in-place BN + ReLU, 8 float4 per iter.
__global__ void bn_k(const float* __restrict__ gamma,
                     const float* __restrict__ beta,
                     float* __restrict__ out){
    __shared__ float sc[TT], sh[TT];
    for (int t = threadIdx.x; t < TT; t += blockDim.x){
        float mean = g_stats[t] / CNT;
        float var  = g_stats[TT + t] / CNT - mean*mean;
        float s    = rsqrtf(var + 1e-5f) * gamma[t];
        sc[t] = s;
        sh[t] = beta[t] - mean*s;
    }
    __syncthreads();

    const int total32 = (NB*TT*NN*CC)/32;   // 640,000 groups of 8 float4
    int stride = gridDim.x * blockDim.x;
    for (int i = blockIdx.x*blockDim.x + threadIdx.x; i < total32; i += stride){
        int t = (i / 100) % TT;             // 100 = N*C/32 groups per (b,t)
        float s = sc[t], h = sh[t];
        float4* p = (float4*)out + (size_t)i*8;
        float4 v[8];
        #pragma unroll
        for (int q = 0; q < 8; q++) v[q] = p[q];
        #pragma unroll
        for (int q = 0; q < 8; q++){
            v[q].x = fmaxf(fmaf(v[q].x, s, h), 0.0f);
            v[q].y = fmaxf(fmaf(v[q].y, s, h), 0.0f);
            v[q].z = fmaxf(fmaf(v[q].z, s, h), 0.0f);
            v[q].w = fmaxf(fmaf(v[q].w, s, h), 0.0f);
        }
        #pragma unroll
        for (int q = 0; q < 8; q++) p[q] = v[q];
    }
}

extern "C" void kernel_launch(void* const* d_in, const int* in_sizes, int n_in,
                              void* d_out, int out_size){
    const float* x  = (const float*)d_in[0];
    const int*   ei = (const int*)  d_in[1];
    const float* W1 = (const float*)d_in[2];
    const float* b1 = (const float*)d_in[3];
    const float* W2 = (const float*)d_in[4];
    const float* b2 = (const float*)d_in[5];
    const float* ga = (const float*)d_in[6];
    const float* be = (const float*)d_in[7];
    float* out = (float*)d_out;

    int nsm = 148;
    cudaDeviceGetAttribute(&nsm, cudaDevAttrMultiProcessorCount, 0);

    const int smemB = (WS_F + XV_F + A2_F + 32 + 2*CC) * (int)sizeof(float);
    cudaFuncSetAttribute(gcn_k, cudaFuncAttributeMaxDynamicSharedMemorySize, smemB);

    prep_k<<<CC, 256>>>(ei, W1, W2, b1);
    gcn_k<<<nsm, 256, smemB>>>(x, b2, out);
    bn_k<<<nsm*8, 256>>>(ga, be, out);
}